// round 2
// baseline (speedup 1.0000x reference)
#include <cuda_runtime.h>

#define N_NODES 20000
#define N_EDGES 640000
#define C 128
#define NUM_GRAPHS 64

// ---------------- scratch (no allocations allowed) ----------------
__device__ float g_agg[N_NODES * C];   // holds x + sum_{edges} feat[src]
__device__ float g_t[N_NODES * C];     // intermediate after first MLP linear
__device__ float g_h[N_NODES * C];     // h1 (output of conv1 + relu)
__device__ float g_gsum[NUM_GRAPHS * C];
__device__ float g_gcnt[NUM_GRAPHS];
__device__ int   g_src[N_EDGES];
__device__ int   g_dst[N_EDGES];
__device__ int   g_batch[N_NODES];
__device__ int   g_is64;

// ---------------- index dtype detection + conversion ----------------
// If edge_index is int64 (little-endian, values < 2^31), every odd 32-bit
// word is 0. If int32, odd words are random node ids (certainly nonzero
// across 64 samples).
__global__ void detect_kernel(const int* __restrict__ idx) {
    int any = 0;
#pragma unroll
    for (int i = 1; i < 128; i += 2) any |= idx[i];
    g_is64 = (any == 0) ? 1 : 0;
}

__global__ void convert_indices(const void* __restrict__ eidx,
                                const void* __restrict__ batch) {
    int i = blockIdx.x * blockDim.x + threadIdx.x;
    if (g_is64) {
        const long long* e = (const long long*)eidx;
        if (i < N_EDGES) {
            g_src[i] = (int)e[i];
            g_dst[i] = (int)e[N_EDGES + i];
        }
        if (i < N_NODES) g_batch[i] = (int)((const long long*)batch)[i];
    } else {
        const int* e = (const int*)eidx;
        if (i < N_EDGES) {
            g_src[i] = e[i];
            g_dst[i] = e[N_EDGES + i];
        }
        if (i < N_NODES) g_batch[i] = ((const int*)batch)[i];
    }
}

// ---------------- init agg = feat (folds the "+x" of GIN eps=0) ----------------
__global__ void copy_feat(const float* __restrict__ src) {
    int i = blockIdx.x * blockDim.x + threadIdx.x;   // float4 index
    if (i < N_NODES * C / 4)
        ((float4*)g_agg)[i] = ((const float4*)src)[i];
}

// ---------------- scatter: agg[dst] += feat[src], one warp per edge ----------------
__global__ void __launch_bounds__(256) scatter_add(const float* __restrict__ feat) {
    int e = blockIdx.x * 8 + (threadIdx.x >> 5);
    if (e >= N_EDGES) return;
    int lane = threadIdx.x & 31;
    int s = g_src[e];
    int d = g_dst[e];
    float4 v = ((const float4*)(feat + (size_t)s * C))[lane];
    float* dp = g_agg + (size_t)d * C + lane * 4;
    atomicAdd(dp + 0, v.x);
    atomicAdd(dp + 1, v.y);
    atomicAdd(dp + 2, v.z);
    atomicAdd(dp + 3, v.w);
}

// ---------------- GEMM: out = relu(A @ W + b), optionally pooled ----------------
// A: [M,128], W: [128,128] row-major (k-major, matching h @ W), b: [128].
// Tile: 64 rows/block, 256 threads, thread = 4 rows x 8 cols.
// do_pool: instead of storing, atomicAdd relu result into g_gsum[batch[m]].
#define GEMM_ROWS 64
#define ASTR 132                      // padded A-tile stride (16B aligned, conflict-free)
#define GEMM_SMEM (128 * 128 * 4 + GEMM_ROWS * ASTR * 4)

__global__ void __launch_bounds__(256) gemm_bias_relu(
    const float* __restrict__ A, const float* __restrict__ W,
    const float* __restrict__ bias, float* __restrict__ out, int do_pool)
{
    extern __shared__ float sm[];
    float* Ws = sm;                   // [128][128]
    float* As = sm + 128 * 128;       // [64][ASTR]

    const int t  = threadIdx.x;
    const int m0 = blockIdx.x * GEMM_ROWS;

    // load W (4096 float4)
#pragma unroll
    for (int i = 0; i < 16; ++i) {
        int idx = t + i * 256;
        ((float4*)Ws)[idx] = ((const float4*)W)[idx];
    }
    // load A tile (2048 float4), zero-pad past M
#pragma unroll
    for (int i = 0; i < 8; ++i) {
        int idx = t + i * 256;
        int r = idx >> 5;             // 0..63
        int c4 = idx & 31;            // float4 col
        float4 v = make_float4(0.f, 0.f, 0.f, 0.f);
        int m = m0 + r;
        if (m < N_NODES) v = ((const float4*)(A + (size_t)m * C))[c4];
        *((float4*)&As[r * ASTR + c4 * 4]) = v;
    }
    __syncthreads();

    const int tx = t & 15;            // col group: cols tx*8 .. +7
    const int ty = t >> 4;            // row group: rows ty*4 .. +3

    float acc[4][8];
#pragma unroll
    for (int i = 0; i < 4; ++i)
#pragma unroll
        for (int j = 0; j < 8; ++j) acc[i][j] = 0.f;

#pragma unroll 8
    for (int k = 0; k < 128; ++k) {
        float a[4];
#pragma unroll
        for (int i = 0; i < 4; ++i) a[i] = As[(ty * 4 + i) * ASTR + k];
        float4 w0 = *((const float4*)&Ws[k * 128 + tx * 8]);
        float4 w1 = *((const float4*)&Ws[k * 128 + tx * 8 + 4]);
#pragma unroll
        for (int i = 0; i < 4; ++i) {
            acc[i][0] += a[i] * w0.x;
            acc[i][1] += a[i] * w0.y;
            acc[i][2] += a[i] * w0.z;
            acc[i][3] += a[i] * w0.w;
            acc[i][4] += a[i] * w1.x;
            acc[i][5] += a[i] * w1.y;
            acc[i][6] += a[i] * w1.z;
            acc[i][7] += a[i] * w1.w;
        }
    }

    float4 b0 = *((const float4*)&bias[tx * 8]);
    float4 b1 = *((const float4*)&bias[tx * 8 + 4]);
    float bb[8] = {b0.x, b0.y, b0.z, b0.w, b1.x, b1.y, b1.z, b1.w};

#pragma unroll
    for (int i = 0; i < 4; ++i) {
        int m = m0 + ty * 4 + i;
        if (m >= N_NODES) continue;
        float r[8];
#pragma unroll
        for (int j = 0; j < 8; ++j) r[j] = fmaxf(acc[i][j] + bb[j], 0.f);
        if (do_pool) {
            int g = g_batch[m];
            float* gp = &g_gsum[g * C + tx * 8];
#pragma unroll
            for (int j = 0; j < 8; ++j) atomicAdd(gp + j, r[j]);
        } else {
            float* op = out + (size_t)m * C + tx * 8;
            *((float4*)op)     = make_float4(r[0], r[1], r[2], r[3]);
            *((float4*)(op+4)) = make_float4(r[4], r[5], r[6], r[7]);
        }
    }
}

// ---------------- pooling support ----------------
__global__ void pool_init() {
    int i = blockIdx.x * blockDim.x + threadIdx.x;
    if (i < NUM_GRAPHS * C) g_gsum[i] = 0.f;
    if (i < NUM_GRAPHS) g_gcnt[i] = 0.f;
}

__global__ void count_nodes() {
    int i = blockIdx.x * blockDim.x + threadIdx.x;
    if (i < N_NODES) atomicAdd(&g_gcnt[g_batch[i]], 1.0f);
}

__global__ void finalize_kernel(const float* __restrict__ fc_w,
                                const float* __restrict__ fc_b,
                                float* __restrict__ out) {
    int g = blockIdx.x;
    int t = threadIdx.x;  // 128
    float v = g_gsum[g * C + t] * fc_w[t];
#pragma unroll
    for (int o = 16; o > 0; o >>= 1) v += __shfl_down_sync(0xFFFFFFFFu, v, o);
    __shared__ float ws[4];
    if ((t & 31) == 0) ws[t >> 5] = v;
    __syncthreads();
    if (t == 0) {
        float s = ws[0] + ws[1] + ws[2] + ws[3];
        out[g] = s / fmaxf(g_gcnt[g], 1.0f) + fc_b[0];
    }
}

// ---------------- launch ----------------
extern "C" void kernel_launch(void* const* d_in, const int* in_sizes, int n_in,
                              void* d_out, int out_size) {
    const float* x    = (const float*)d_in[0];
    const void*  eidx = d_in[1];
    const void*  batv = d_in[2];
    const float* W1a  = (const float*)d_in[3];
    const float* b1a  = (const float*)d_in[4];
    const float* W1b  = (const float*)d_in[5];
    const float* b1b  = (const float*)d_in[6];
    const float* W2a  = (const float*)d_in[7];
    const float* b2a  = (const float*)d_in[8];
    const float* W2b  = (const float*)d_in[9];
    const float* b2b  = (const float*)d_in[10];
    const float* fcw  = (const float*)d_in[11];
    const float* fcb  = (const float*)d_in[12];
    float* out = (float*)d_out;
    (void)in_sizes; (void)n_in; (void)out_size;

    cudaFuncSetAttribute(gemm_bias_relu,
                         cudaFuncAttributeMaxDynamicSharedMemorySize, GEMM_SMEM);

    float *p_agg, *p_t, *p_h;
    cudaGetSymbolAddress((void**)&p_agg, g_agg);
    cudaGetSymbolAddress((void**)&p_t,   g_t);
    cudaGetSymbolAddress((void**)&p_h,   g_h);

    const int gemm_blocks = (N_NODES + GEMM_ROWS - 1) / GEMM_ROWS;

    detect_kernel<<<1, 1>>>((const int*)eidx);
    convert_indices<<<(N_EDGES + 255) / 256, 256>>>(eidx, batv);

    // ---- conv1: agg = x + sum x[src] ; h1 = relu(relu(agg@W1a+b1a)@W1b+b1b)
    copy_feat<<<(N_NODES * C / 4 + 255) / 256, 256>>>(x);
    scatter_add<<<(N_EDGES + 7) / 8, 256>>>(x);
    gemm_bias_relu<<<gemm_blocks, 256, GEMM_SMEM>>>(p_agg, W1a, b1a, p_t, 0);
    gemm_bias_relu<<<gemm_blocks, 256, GEMM_SMEM>>>(p_t,   W1b, b1b, p_h, 0);

    // ---- pooling accumulators (ready before last GEMM's fused pool)
    pool_init<<<(NUM_GRAPHS * C + 255) / 256, 256>>>();
    count_nodes<<<(N_NODES + 255) / 256, 256>>>();

    // ---- conv2: agg = h1 + sum h1[src] ; fused pool in final GEMM epilogue
    copy_feat<<<(N_NODES * C / 4 + 255) / 256, 256>>>(p_h);
    scatter_add<<<(N_EDGES + 7) / 8, 256>>>(p_h);
    gemm_bias_relu<<<gemm_blocks, 256, GEMM_SMEM>>>(p_agg, W2a, b2a, p_t, 0);
    gemm_bias_relu<<<gemm_blocks, 256, GEMM_SMEM>>>(p_t,   W2b, b2b, nullptr, 1);

    // ---- out[g] = (gsum[g]/cnt[g]) . fc_w + fc_b
    finalize_kernel<<<NUM_GRAPHS, C>>>(fcw, fcb, out);
}

// round 3
// speedup vs baseline: 1.8504x; 1.8504x over previous
#include <cuda_runtime.h>

#define N_NODES 20000
#define N_EDGES 640000
#define C 128
#define NUM_GRAPHS 64

// ---------------- scratch (no allocations allowed) ----------------
__device__ float g_agg[N_NODES * C];   // x + sum_{in-edges} feat[src]
__device__ float g_t[N_NODES * C];     // intermediate after first MLP linear
__device__ float g_h[N_NODES * C];     // h1 (conv1 output)
__device__ float g_gsum[NUM_GRAPHS * C];
__device__ float g_gcnt[NUM_GRAPHS];
__device__ int   g_src[N_EDGES];
__device__ int   g_dst[N_EDGES];
__device__ int   g_csrc[N_EDGES];      // CSR: src ids grouped by dst
__device__ int   g_off[N_NODES + 1];   // CSR row offsets
__device__ int   g_cur[N_NODES];       // fill cursors
__device__ int   g_deg[N_NODES];
__device__ int   g_batch[N_NODES];
__device__ int   g_is64;

// ---------------- index dtype detection ----------------
// int64 little-endian with values < 2^31 => every odd 32-bit word is 0.
__global__ void detect_kernel(const int* __restrict__ idx) {
    int any = 0;
#pragma unroll
    for (int i = 1; i < 128; i += 2) any |= idx[i];
    g_is64 = (any == 0) ? 1 : 0;
}

// convert indices + zero degree array + degree histogram, one pass
__global__ void convert_and_count(const void* __restrict__ eidx,
                                  const void* __restrict__ batch) {
    int i = blockIdx.x * blockDim.x + threadIdx.x;
    if (i < N_NODES) g_deg[i] = 0;
    __threadfence();  // not strictly needed across kernels; histogram is below via separate pass
}

__global__ void convert_indices(const void* __restrict__ eidx,
                                const void* __restrict__ batch) {
    int i = blockIdx.x * blockDim.x + threadIdx.x;
    if (g_is64) {
        const long long* e = (const long long*)eidx;
        if (i < N_EDGES) {
            int s = (int)e[i];
            int d = (int)e[N_EDGES + i];
            g_src[i] = s; g_dst[i] = d;
            atomicAdd(&g_deg[d], 1);
        }
        if (i < N_NODES) g_batch[i] = (int)((const long long*)batch)[i];
    } else {
        const int* e = (const int*)eidx;
        if (i < N_EDGES) {
            int s = e[i];
            int d = e[N_EDGES + i];
            g_src[i] = s; g_dst[i] = d;
            atomicAdd(&g_deg[d], 1);
        }
        if (i < N_NODES) g_batch[i] = ((const int*)batch)[i];
    }
}

__global__ void zero_deg() {
    int i = blockIdx.x * blockDim.x + threadIdx.x;
    if (i < N_NODES) g_deg[i] = 0;
}

// ---------------- single-block exclusive scan over degrees ----------------
__global__ void __launch_bounds__(1024) scan_deg() {
    __shared__ int part[1024];
    const int t = threadIdx.x;
    const int per = (N_NODES + 1023) / 1024;   // 20
    const int base = t * per;
    int s = 0;
    for (int i = 0; i < per; ++i) {
        int idx = base + i;
        if (idx < N_NODES) s += g_deg[idx];
    }
    part[t] = s;
    __syncthreads();
    for (int o = 1; o < 1024; o <<= 1) {
        int v = 0;
        if (t >= o) v = part[t - o];
        __syncthreads();
        if (t >= o) part[t] += v;
        __syncthreads();
    }
    int off = (t == 0) ? 0 : part[t - 1];
    for (int i = 0; i < per; ++i) {
        int idx = base + i;
        if (idx < N_NODES) {
            int d = g_deg[idx];
            g_off[idx] = off;
            g_cur[idx] = off;
            off += d;
        }
    }
    if (t == 0) g_off[N_NODES] = N_EDGES;
}

__global__ void fill_csr() {
    int i = blockIdx.x * blockDim.x + threadIdx.x;
    if (i < N_EDGES) {
        int d = g_dst[i];
        int p = atomicAdd(&g_cur[d], 1);
        g_csrc[p] = g_src[i];
    }
}

// ---------------- gather: agg[n] = feat[n] + sum_{e in CSR(n)} feat[src] ----------------
// warp per node; lane owns one float4 column slice. No fp atomics.
__global__ void __launch_bounds__(256) gather_agg(const float* __restrict__ feat) {
    int node = blockIdx.x * 8 + (threadIdx.x >> 5);
    if (node >= N_NODES) return;
    const int lane = threadIdx.x & 31;
    const float4* fp = (const float4*)feat;

    int beg = g_off[node];
    int end = g_off[node + 1];

    float4 acc = fp[(size_t)node * 32 + lane];   // folds the "+x" of GIN eps=0

    int e = beg;
    for (; e + 4 <= end; e += 4) {
        int s0 = g_csrc[e + 0];
        int s1 = g_csrc[e + 1];
        int s2 = g_csrc[e + 2];
        int s3 = g_csrc[e + 3];
        float4 v0 = fp[(size_t)s0 * 32 + lane];
        float4 v1 = fp[(size_t)s1 * 32 + lane];
        float4 v2 = fp[(size_t)s2 * 32 + lane];
        float4 v3 = fp[(size_t)s3 * 32 + lane];
        acc.x += v0.x + v1.x + v2.x + v3.x;
        acc.y += v0.y + v1.y + v2.y + v3.y;
        acc.z += v0.z + v1.z + v2.z + v3.z;
        acc.w += v0.w + v1.w + v2.w + v3.w;
    }
    for (; e < end; ++e) {
        int s = g_csrc[e];
        float4 v = fp[(size_t)s * 32 + lane];
        acc.x += v.x; acc.y += v.y; acc.z += v.z; acc.w += v.w;
    }
    ((float4*)g_agg)[(size_t)node * 32 + lane] = acc;
}

// ---------------- GEMM: out = relu(A @ W + b), optionally pooled ----------------
#define GEMM_ROWS 64
#define ASTR 132
#define GEMM_SMEM (128 * 128 * 4 + GEMM_ROWS * ASTR * 4)

__global__ void __launch_bounds__(256) gemm_bias_relu(
    const float* __restrict__ A, const float* __restrict__ W,
    const float* __restrict__ bias, float* __restrict__ out, int do_pool)
{
    extern __shared__ float sm[];
    float* Ws = sm;                   // [128][128]
    float* As = sm + 128 * 128;       // [64][ASTR]

    const int t  = threadIdx.x;
    const int m0 = blockIdx.x * GEMM_ROWS;

#pragma unroll
    for (int i = 0; i < 16; ++i) {
        int idx = t + i * 256;
        ((float4*)Ws)[idx] = ((const float4*)W)[idx];
    }
#pragma unroll
    for (int i = 0; i < 8; ++i) {
        int idx = t + i * 256;
        int r = idx >> 5;
        int c4 = idx & 31;
        float4 v = make_float4(0.f, 0.f, 0.f, 0.f);
        int m = m0 + r;
        if (m < N_NODES) v = ((const float4*)(A + (size_t)m * C))[c4];
        *((float4*)&As[r * ASTR + c4 * 4]) = v;
    }
    __syncthreads();

    const int tx = t & 15;
    const int ty = t >> 4;

    float acc[4][8];
#pragma unroll
    for (int i = 0; i < 4; ++i)
#pragma unroll
        for (int j = 0; j < 8; ++j) acc[i][j] = 0.f;

#pragma unroll 8
    for (int k = 0; k < 128; ++k) {
        float a[4];
#pragma unroll
        for (int i = 0; i < 4; ++i) a[i] = As[(ty * 4 + i) * ASTR + k];
        float4 w0 = *((const float4*)&Ws[k * 128 + tx * 8]);
        float4 w1 = *((const float4*)&Ws[k * 128 + tx * 8 + 4]);
#pragma unroll
        for (int i = 0; i < 4; ++i) {
            acc[i][0] += a[i] * w0.x;
            acc[i][1] += a[i] * w0.y;
            acc[i][2] += a[i] * w0.z;
            acc[i][3] += a[i] * w0.w;
            acc[i][4] += a[i] * w1.x;
            acc[i][5] += a[i] * w1.y;
            acc[i][6] += a[i] * w1.z;
            acc[i][7] += a[i] * w1.w;
        }
    }

    float4 b0 = *((const float4*)&bias[tx * 8]);
    float4 b1 = *((const float4*)&bias[tx * 8 + 4]);
    float bb[8] = {b0.x, b0.y, b0.z, b0.w, b1.x, b1.y, b1.z, b1.w};

#pragma unroll
    for (int i = 0; i < 4; ++i) {
        int m = m0 + ty * 4 + i;
        if (m >= N_NODES) continue;
        float r[8];
#pragma unroll
        for (int j = 0; j < 8; ++j) r[j] = fmaxf(acc[i][j] + bb[j], 0.f);
        if (do_pool) {
            int g = g_batch[m];
            float* gp = &g_gsum[g * C + tx * 8];
#pragma unroll
            for (int j = 0; j < 8; ++j) atomicAdd(gp + j, r[j]);
        } else {
            float* op = out + (size_t)m * C + tx * 8;
            *((float4*)op)     = make_float4(r[0], r[1], r[2], r[3]);
            *((float4*)(op+4)) = make_float4(r[4], r[5], r[6], r[7]);
        }
    }
}

// ---------------- pooling support ----------------
__global__ void pool_init() {
    int i = blockIdx.x * blockDim.x + threadIdx.x;
    if (i < NUM_GRAPHS * C) g_gsum[i] = 0.f;
    if (i < NUM_GRAPHS) g_gcnt[i] = 0.f;
}

__global__ void count_nodes() {
    int i = blockIdx.x * blockDim.x + threadIdx.x;
    if (i < N_NODES) atomicAdd(&g_gcnt[g_batch[i]], 1.0f);
}

__global__ void finalize_kernel(const float* __restrict__ fc_w,
                                const float* __restrict__ fc_b,
                                float* __restrict__ out) {
    int g = blockIdx.x;
    int t = threadIdx.x;  // 128
    float v = g_gsum[g * C + t] * fc_w[t];
#pragma unroll
    for (int o = 16; o > 0; o >>= 1) v += __shfl_down_sync(0xFFFFFFFFu, v, o);
    __shared__ float ws[4];
    if ((t & 31) == 0) ws[t >> 5] = v;
    __syncthreads();
    if (t == 0) {
        float s = ws[0] + ws[1] + ws[2] + ws[3];
        out[g] = s / fmaxf(g_gcnt[g], 1.0f) + fc_b[0];
    }
}

// ---------------- launch ----------------
extern "C" void kernel_launch(void* const* d_in, const int* in_sizes, int n_in,
                              void* d_out, int out_size) {
    const float* x    = (const float*)d_in[0];
    const void*  eidx = d_in[1];
    const void*  batv = d_in[2];
    const float* W1a  = (const float*)d_in[3];
    const float* b1a  = (const float*)d_in[4];
    const float* W1b  = (const float*)d_in[5];
    const float* b1b  = (const float*)d_in[6];
    const float* W2a  = (const float*)d_in[7];
    const float* b2a  = (const float*)d_in[8];
    const float* W2b  = (const float*)d_in[9];
    const float* b2b  = (const float*)d_in[10];
    const float* fcw  = (const float*)d_in[11];
    const float* fcb  = (const float*)d_in[12];
    float* out = (float*)d_out;
    (void)in_sizes; (void)n_in; (void)out_size;

    cudaFuncSetAttribute(gemm_bias_relu,
                         cudaFuncAttributeMaxDynamicSharedMemorySize, GEMM_SMEM);

    float *p_agg, *p_t, *p_h;
    cudaGetSymbolAddress((void**)&p_agg, g_agg);
    cudaGetSymbolAddress((void**)&p_t,   g_t);
    cudaGetSymbolAddress((void**)&p_h,   g_h);

    const int gemm_blocks = (N_NODES + GEMM_ROWS - 1) / GEMM_ROWS;

    // ---- CSR build (once per launch; reused by both conv layers)
    detect_kernel<<<1, 1>>>((const int*)eidx);
    zero_deg<<<(N_NODES + 255) / 256, 256>>>();
    convert_indices<<<(N_EDGES + 255) / 256, 256>>>(eidx, batv);
    scan_deg<<<1, 1024>>>();
    fill_csr<<<(N_EDGES + 255) / 256, 256>>>();

    // ---- conv1
    gather_agg<<<(N_NODES + 7) / 8, 256>>>(x);
    gemm_bias_relu<<<gemm_blocks, 256, GEMM_SMEM>>>(p_agg, W1a, b1a, p_t, 0);
    gemm_bias_relu<<<gemm_blocks, 256, GEMM_SMEM>>>(p_t,   W1b, b1b, p_h, 0);

    // ---- pooling accumulators (ready before last GEMM's fused pool)
    pool_init<<<(NUM_GRAPHS * C + 255) / 256, 256>>>();
    count_nodes<<<(N_NODES + 255) / 256, 256>>>();

    // ---- conv2 (fused pool in final GEMM epilogue)
    gather_agg<<<(N_NODES + 7) / 8, 256>>>(p_h);
    gemm_bias_relu<<<gemm_blocks, 256, GEMM_SMEM>>>(p_agg, W2a, b2a, p_t, 0);
    gemm_bias_relu<<<gemm_blocks, 256, GEMM_SMEM>>>(p_t,   W2b, b2b, nullptr, 1);

    // ---- out[g] = (gsum[g]/cnt[g]) . fc_w + fc_b
    finalize_kernel<<<NUM_GRAPHS, C>>>(fcw, fcb, out);
}

// round 4
// speedup vs baseline: 2.1739x; 1.1748x over previous
#include <cuda_runtime.h>

#define N_NODES 20000
#define N_EDGES 640000
#define C 128
#define NUM_GRAPHS 64

// ---------------- scratch (no allocations allowed) ----------------
__device__ float g_h[N_NODES * C];     // h1 (conv1 output)
__device__ float g_gsum[NUM_GRAPHS * C];
__device__ float g_gcnt[NUM_GRAPHS];
__device__ int   g_src[N_EDGES];
__device__ int   g_dst[N_EDGES];
__device__ int   g_csrc[N_EDGES];      // CSR: src ids grouped by dst
__device__ int   g_off[N_NODES + 1];   // CSR row offsets
__device__ int   g_cur[N_NODES];       // fill cursors
__device__ int   g_deg[N_NODES];
__device__ int   g_batch[N_NODES];
__device__ int   g_is64;

// ---------------- setup: zero accumulators + detect index dtype ----------------
// int64 little-endian with node ids < 2^31 => every odd 32-bit word is 0.
__global__ void setup_kernel(const int* __restrict__ eidx_raw) {
    int i = blockIdx.x * blockDim.x + threadIdx.x;
    if (i < N_NODES) g_deg[i] = 0;
    if (i < NUM_GRAPHS * C) g_gsum[i] = 0.f;
    if (i < NUM_GRAPHS) g_gcnt[i] = 0.f;
    if (i == 0) {
        int any = 0;
#pragma unroll
        for (int k = 1; k < 128; k += 2) any |= eidx_raw[k];
        g_is64 = (any == 0) ? 1 : 0;
    }
}

// ---------------- convert indices + degree histogram + graph counts ----------------
__global__ void convert_indices(const void* __restrict__ eidx,
                                const void* __restrict__ batch) {
    int i = blockIdx.x * blockDim.x + threadIdx.x;
    if (g_is64) {
        const long long* e = (const long long*)eidx;
        if (i < N_EDGES) {
            int s = (int)e[i];
            int d = (int)e[N_EDGES + i];
            g_src[i] = s; g_dst[i] = d;
            atomicAdd(&g_deg[d], 1);
        }
        if (i < N_NODES) {
            int g = (int)((const long long*)batch)[i];
            g_batch[i] = g;
            atomicAdd(&g_gcnt[g], 1.0f);
        }
    } else {
        const int* e = (const int*)eidx;
        if (i < N_EDGES) {
            int s = e[i];
            int d = e[N_EDGES + i];
            g_src[i] = s; g_dst[i] = d;
            atomicAdd(&g_deg[d], 1);
        }
        if (i < N_NODES) {
            int g = ((const int*)batch)[i];
            g_batch[i] = g;
            atomicAdd(&g_gcnt[g], 1.0f);
        }
    }
}

// ---------------- single-block scan, smem-staged (coalesced) ----------------
#define SCAN_SMEM (N_NODES * 4)
__global__ void __launch_bounds__(1024) scan_deg() {
    extern __shared__ int sdeg[];          // [N_NODES]
    __shared__ int part[1024];
    const int t = threadIdx.x;
    const int per = (N_NODES + 1023) / 1024;   // 20

    // coalesced load of degrees into smem
    for (int i = t; i < N_NODES; i += 1024) sdeg[i] = g_deg[i];
    __syncthreads();

    // per-thread chunk sum (from smem, latency-free)
    const int base = t * per;
    int s = 0;
#pragma unroll
    for (int i = 0; i < per; ++i) {
        int idx = base + i;
        if (idx < N_NODES) s += sdeg[idx];
    }
    part[t] = s;
    __syncthreads();
    for (int o = 1; o < 1024; o <<= 1) {
        int v = 0;
        if (t >= o) v = part[t - o];
        __syncthreads();
        if (t >= o) part[t] += v;
        __syncthreads();
    }
    // per-element exclusive prefix within chunk, in smem
    int off = (t == 0) ? 0 : part[t - 1];
#pragma unroll
    for (int i = 0; i < per; ++i) {
        int idx = base + i;
        if (idx < N_NODES) {
            int d = sdeg[idx];
            sdeg[idx] = off;
            off += d;
        }
    }
    __syncthreads();
    // coalesced writeback
    for (int i = t; i < N_NODES; i += 1024) {
        int v = sdeg[i];
        g_off[i] = v;
        g_cur[i] = v;
    }
    if (t == 0) g_off[N_NODES] = N_EDGES;
}

__global__ void fill_csr() {
    int i = blockIdx.x * blockDim.x + threadIdx.x;
    if (i < N_EDGES) {
        int d = g_dst[i];
        int p = atomicAdd(&g_cur[d], 1);
        g_csrc[p] = g_src[i];
    }
}

// ---------------- fused conv layer ----------------
// One kernel per GIN layer:
//   agg  = feat[n] + sum_{CSR(n)} feat[src]          (gather, regs -> As smem)
//   t    = relu(agg @ Wa + ba)                        (GEMM1, acc in regs)
//   h    = relu(t @ Wb + bb)                          (GEMM2)
//   h -> out, or atomic pool into g_gsum (do_pool)
// smem: Ws[128][128] (Wa then Wb, reloaded) + tile[64][ASTR] (As then Ts).
#define GEMM_ROWS 64
#define ASTR 132
#define CONV_SMEM ((128 * 128 + GEMM_ROWS * ASTR) * 4)

__global__ void __launch_bounds__(256, 2) fused_conv(
    const float* __restrict__ feat,
    const float* __restrict__ Wa, const float* __restrict__ ba,
    const float* __restrict__ Wb, const float* __restrict__ bb,
    float* __restrict__ out, int do_pool)
{
    extern __shared__ float sm[];
    float* Ws = sm;                        // [128][128]
    float* Ts = sm + 128 * 128;            // [64][ASTR], As then Ts

    const int t  = threadIdx.x;
    const int m0 = blockIdx.x * GEMM_ROWS;
    const int lane = t & 31;
    const int w = t >> 5;                  // warp 0..7

    // ---- load Wa (4096 float4, coalesced)
#pragma unroll
    for (int i = 0; i < 16; ++i) {
        int idx = t + i * 256;
        ((float4*)Ws)[idx] = ((const float4*)Wa)[idx];
    }

    // ---- gather: warp per node, 8 nodes per warp
    const float4* fp = (const float4*)feat;
#pragma unroll
    for (int i = 0; i < 8; ++i) {
        int r = w * 8 + i;                 // local row 0..63
        int node = m0 + r;
        float4 acc = make_float4(0.f, 0.f, 0.f, 0.f);
        if (node < N_NODES) {
            acc = fp[(size_t)node * 32 + lane];    // folds "+x" (GIN eps=0)
            int e = g_off[node];
            int end = g_off[node + 1];
            for (; e + 4 <= end; e += 4) {
                int s0 = g_csrc[e + 0];
                int s1 = g_csrc[e + 1];
                int s2 = g_csrc[e + 2];
                int s3 = g_csrc[e + 3];
                float4 v0 = fp[(size_t)s0 * 32 + lane];
                float4 v1 = fp[(size_t)s1 * 32 + lane];
                float4 v2 = fp[(size_t)s2 * 32 + lane];
                float4 v3 = fp[(size_t)s3 * 32 + lane];
                acc.x += v0.x + v1.x + v2.x + v3.x;
                acc.y += v0.y + v1.y + v2.y + v3.y;
                acc.z += v0.z + v1.z + v2.z + v3.z;
                acc.w += v0.w + v1.w + v2.w + v3.w;
            }
            for (; e < end; ++e) {
                int s = g_csrc[e];
                float4 v = fp[(size_t)s * 32 + lane];
                acc.x += v.x; acc.y += v.y; acc.z += v.z; acc.w += v.w;
            }
        }
        *((float4*)&Ts[r * ASTR + lane * 4]) = acc;   // Ts buffer holds As now
    }
    __syncthreads();

    const int tx = t & 15;                 // cols tx*8 .. +7
    const int ty = t >> 4;                 // rows ty*4 .. +3

    float acc[4][8];
#pragma unroll
    for (int i = 0; i < 4; ++i)
#pragma unroll
        for (int j = 0; j < 8; ++j) acc[i][j] = 0.f;

    // ---- GEMM1: acc = As @ Wa
#pragma unroll 8
    for (int k = 0; k < 128; ++k) {
        float a[4];
#pragma unroll
        for (int i = 0; i < 4; ++i) a[i] = Ts[(ty * 4 + i) * ASTR + k];
        float4 w0 = *((const float4*)&Ws[k * 128 + tx * 8]);
        float4 w1 = *((const float4*)&Ws[k * 128 + tx * 8 + 4]);
#pragma unroll
        for (int i = 0; i < 4; ++i) {
            acc[i][0] += a[i] * w0.x; acc[i][1] += a[i] * w0.y;
            acc[i][2] += a[i] * w0.z; acc[i][3] += a[i] * w0.w;
            acc[i][4] += a[i] * w1.x; acc[i][5] += a[i] * w1.y;
            acc[i][6] += a[i] * w1.z; acc[i][7] += a[i] * w1.w;
        }
    }
    __syncthreads();   // all reads of As / Wa done

    // ---- bias + relu, write t-tile over As; load Wb over Wa
    {
        float4 b0 = *((const float4*)&ba[tx * 8]);
        float4 b1 = *((const float4*)&ba[tx * 8 + 4]);
        float bbv[8] = {b0.x, b0.y, b0.z, b0.w, b1.x, b1.y, b1.z, b1.w};
#pragma unroll
        for (int i = 0; i < 4; ++i) {
            int r = ty * 4 + i;
            float* tp = &Ts[r * ASTR + tx * 8];
            float v0x = fmaxf(acc[i][0] + bbv[0], 0.f);
            float v0y = fmaxf(acc[i][1] + bbv[1], 0.f);
            float v0z = fmaxf(acc[i][2] + bbv[2], 0.f);
            float v0w = fmaxf(acc[i][3] + bbv[3], 0.f);
            float v1x = fmaxf(acc[i][4] + bbv[4], 0.f);
            float v1y = fmaxf(acc[i][5] + bbv[5], 0.f);
            float v1z = fmaxf(acc[i][6] + bbv[6], 0.f);
            float v1w = fmaxf(acc[i][7] + bbv[7], 0.f);
            *((float4*)tp)       = make_float4(v0x, v0y, v0z, v0w);
            *((float4*)(tp + 4)) = make_float4(v1x, v1y, v1z, v1w);
        }
    }
#pragma unroll
    for (int i = 0; i < 16; ++i) {
        int idx = t + i * 256;
        ((float4*)Ws)[idx] = ((const float4*)Wb)[idx];
    }
    __syncthreads();

    // ---- GEMM2: acc = Ts @ Wb
#pragma unroll
    for (int i = 0; i < 4; ++i)
#pragma unroll
        for (int j = 0; j < 8; ++j) acc[i][j] = 0.f;

#pragma unroll 8
    for (int k = 0; k < 128; ++k) {
        float a[4];
#pragma unroll
        for (int i = 0; i < 4; ++i) a[i] = Ts[(ty * 4 + i) * ASTR + k];
        float4 w0 = *((const float4*)&Ws[k * 128 + tx * 8]);
        float4 w1 = *((const float4*)&Ws[k * 128 + tx * 8 + 4]);
#pragma unroll
        for (int i = 0; i < 4; ++i) {
            acc[i][0] += a[i] * w0.x; acc[i][1] += a[i] * w0.y;
            acc[i][2] += a[i] * w0.z; acc[i][3] += a[i] * w0.w;
            acc[i][4] += a[i] * w1.x; acc[i][5] += a[i] * w1.y;
            acc[i][6] += a[i] * w1.z; acc[i][7] += a[i] * w1.w;
        }
    }

    // ---- epilogue: bias + relu, then store or pool
    float4 b0 = *((const float4*)&bb[tx * 8]);
    float4 b1 = *((const float4*)&bb[tx * 8 + 4]);
    float bbv[8] = {b0.x, b0.y, b0.z, b0.w, b1.x, b1.y, b1.z, b1.w};

    float r[4][8];
#pragma unroll
    for (int i = 0; i < 4; ++i)
#pragma unroll
        for (int j = 0; j < 8; ++j) r[i][j] = fmaxf(acc[i][j] + bbv[j], 0.f);

    if (do_pool) {
        // combine consecutive rows with equal graph id -> fewer global atomics
        int i = 0;
        while (i < 4) {
            int m = m0 + ty * 4 + i;
            if (m >= N_NODES) break;
            int g = g_batch[m];
            float s[8];
#pragma unroll
            for (int j = 0; j < 8; ++j) s[j] = r[i][j];
            int i2 = i + 1;
            while (i2 < 4) {
                int m2 = m0 + ty * 4 + i2;
                if (m2 >= N_NODES || g_batch[m2] != g) break;
#pragma unroll
                for (int j = 0; j < 8; ++j) s[j] += r[i2][j];
                ++i2;
            }
            float* gp = &g_gsum[g * C + tx * 8];
#pragma unroll
            for (int j = 0; j < 8; ++j) atomicAdd(gp + j, s[j]);
            i = i2;
        }
    } else {
#pragma unroll
        for (int i = 0; i < 4; ++i) {
            int m = m0 + ty * 4 + i;
            if (m >= N_NODES) continue;
            float* op = out + (size_t)m * C + tx * 8;
            *((float4*)op)       = make_float4(r[i][0], r[i][1], r[i][2], r[i][3]);
            *((float4*)(op + 4)) = make_float4(r[i][4], r[i][5], r[i][6], r[i][7]);
        }
    }
}

// ---------------- finalize: out[g] = (gsum[g]/cnt[g]) . fc_w + fc_b ----------------
__global__ void finalize_kernel(const float* __restrict__ fc_w,
                                const float* __restrict__ fc_b,
                                float* __restrict__ out) {
    int g = blockIdx.x;
    int t = threadIdx.x;  // 128
    float v = g_gsum[g * C + t] * fc_w[t];
#pragma unroll
    for (int o = 16; o > 0; o >>= 1) v += __shfl_down_sync(0xFFFFFFFFu, v, o);
    __shared__ float ws[4];
    if ((t & 31) == 0) ws[t >> 5] = v;
    __syncthreads();
    if (t == 0) {
        float s = ws[0] + ws[1] + ws[2] + ws[3];
        out[g] = s / fmaxf(g_gcnt[g], 1.0f) + fc_b[0];
    }
}

// ---------------- launch ----------------
extern "C" void kernel_launch(void* const* d_in, const int* in_sizes, int n_in,
                              void* d_out, int out_size) {
    const float* x    = (const float*)d_in[0];
    const void*  eidx = d_in[1];
    const void*  batv = d_in[2];
    const float* W1a  = (const float*)d_in[3];
    const float* b1a  = (const float*)d_in[4];
    const float* W1b  = (const float*)d_in[5];
    const float* b1b  = (const float*)d_in[6];
    const float* W2a  = (const float*)d_in[7];
    const float* b2a  = (const float*)d_in[8];
    const float* W2b  = (const float*)d_in[9];
    const float* b2b  = (const float*)d_in[10];
    const float* fcw  = (const float*)d_in[11];
    const float* fcb  = (const float*)d_in[12];
    float* out = (float*)d_out;
    (void)in_sizes; (void)n_in; (void)out_size;

    cudaFuncSetAttribute(fused_conv,
                         cudaFuncAttributeMaxDynamicSharedMemorySize, CONV_SMEM);
    cudaFuncSetAttribute(scan_deg,
                         cudaFuncAttributeMaxDynamicSharedMemorySize, SCAN_SMEM);

    float* p_h;
    cudaGetSymbolAddress((void**)&p_h, g_h);

    const int conv_blocks = (N_NODES + GEMM_ROWS - 1) / GEMM_ROWS;

    // ---- CSR build (once; reused by both layers)
    setup_kernel<<<(N_NODES + 255) / 256, 256>>>((const int*)eidx);
    convert_indices<<<(N_EDGES + 255) / 256, 256>>>(eidx, batv);
    scan_deg<<<1, 1024, SCAN_SMEM>>>();
    fill_csr<<<(N_EDGES + 255) / 256, 256>>>();

    // ---- conv1 (fused gather + MLP)
    fused_conv<<<conv_blocks, 256, CONV_SMEM>>>(x, W1a, b1a, W1b, b1b, p_h, 0);
    // ---- conv2 (fused gather + MLP + pool)
    fused_conv<<<conv_blocks, 256, CONV_SMEM>>>(p_h, W2a, b2a, W2b, b2b, nullptr, 1);

    finalize_kernel<<<NUM_GRAPHS, C>>>(fcw, fcb, out);
}

// round 5
// speedup vs baseline: 3.1379x; 1.4434x over previous
#include <cuda_runtime.h>
#include <cstdint>

#define N_NODES 20000
#define N_EDGES 640000
#define C 128
#define NUM_GRAPHS 64

// ---------------- scratch (no allocations allowed) ----------------
__device__ float g_h[N_NODES * C];     // h1 (conv1 output)
__device__ float g_gsum[NUM_GRAPHS * C];
__device__ float g_gcnt[NUM_GRAPHS];
__device__ int   g_src[N_EDGES];
__device__ int   g_dst[N_EDGES];
__device__ int   g_csrc[N_EDGES];      // CSR: src ids grouped by dst
__device__ int   g_off[N_NODES + 1];   // CSR row offsets
__device__ int   g_cur[N_NODES];       // fill cursors
__device__ int   g_deg[N_NODES];
__device__ int   g_batch[N_NODES];
__device__ int   g_is64;

// ---------------- setup: zero accumulators + detect index dtype ----------------
__global__ void setup_kernel(const int* __restrict__ eidx_raw) {
    int i = blockIdx.x * blockDim.x + threadIdx.x;
    if (i < N_NODES) g_deg[i] = 0;
    if (i < NUM_GRAPHS * C) g_gsum[i] = 0.f;
    if (i < NUM_GRAPHS) g_gcnt[i] = 0.f;
    if (i == 0) {
        int any = 0;
#pragma unroll
        for (int k = 1; k < 128; k += 2) any |= eidx_raw[k];
        g_is64 = (any == 0) ? 1 : 0;
    }
}

// ---------------- convert indices (4 per thread, vector loads) ----------------
__global__ void convert_indices(const void* __restrict__ eidx,
                                const void* __restrict__ batch) {
    int i0 = (blockIdx.x * blockDim.x + threadIdx.x) * 4;
    if (g_is64) {
        const long long* e = (const long long*)eidx;
        if (i0 < N_EDGES) {
            longlong2 s01 = *(const longlong2*)&e[i0];
            longlong2 s23 = *(const longlong2*)&e[i0 + 2];
            longlong2 d01 = *(const longlong2*)&e[N_EDGES + i0];
            longlong2 d23 = *(const longlong2*)&e[N_EDGES + i0 + 2];
            int4 s = make_int4((int)s01.x, (int)s01.y, (int)s23.x, (int)s23.y);
            int4 d = make_int4((int)d01.x, (int)d01.y, (int)d23.x, (int)d23.y);
            *(int4*)&g_src[i0] = s;
            *(int4*)&g_dst[i0] = d;
            atomicAdd(&g_deg[d.x], 1); atomicAdd(&g_deg[d.y], 1);
            atomicAdd(&g_deg[d.z], 1); atomicAdd(&g_deg[d.w], 1);
        }
        if (i0 < N_NODES) {
            const long long* b = (const long long*)batch;
            longlong2 b01 = *(const longlong2*)&b[i0];
            longlong2 b23 = *(const longlong2*)&b[i0 + 2];
            int4 g = make_int4((int)b01.x, (int)b01.y, (int)b23.x, (int)b23.y);
            *(int4*)&g_batch[i0] = g;
            atomicAdd(&g_gcnt[g.x], 1.f); atomicAdd(&g_gcnt[g.y], 1.f);
            atomicAdd(&g_gcnt[g.z], 1.f); atomicAdd(&g_gcnt[g.w], 1.f);
        }
    } else {
        const int* e = (const int*)eidx;
        if (i0 < N_EDGES) {
            int4 s = *(const int4*)&e[i0];
            int4 d = *(const int4*)&e[N_EDGES + i0];
            *(int4*)&g_src[i0] = s;
            *(int4*)&g_dst[i0] = d;
            atomicAdd(&g_deg[d.x], 1); atomicAdd(&g_deg[d.y], 1);
            atomicAdd(&g_deg[d.z], 1); atomicAdd(&g_deg[d.w], 1);
        }
        if (i0 < N_NODES) {
            int4 g = *(const int4*)&((const int*)batch)[i0];
            *(int4*)&g_batch[i0] = g;
            atomicAdd(&g_gcnt[g.x], 1.f); atomicAdd(&g_gcnt[g.y], 1.f);
            atomicAdd(&g_gcnt[g.z], 1.f); atomicAdd(&g_gcnt[g.w], 1.f);
        }
    }
}

// ---------------- single-block scan, smem-staged (coalesced) ----------------
#define SCAN_SMEM (N_NODES * 4)
__global__ void __launch_bounds__(1024) scan_deg() {
    extern __shared__ int sdeg[];
    __shared__ int part[1024];
    const int t = threadIdx.x;
    const int per = (N_NODES + 1023) / 1024;   // 20

    for (int i = t; i < N_NODES; i += 1024) sdeg[i] = g_deg[i];
    __syncthreads();

    const int base = t * per;
    int s = 0;
#pragma unroll
    for (int i = 0; i < per; ++i) {
        int idx = base + i;
        if (idx < N_NODES) s += sdeg[idx];
    }
    part[t] = s;
    __syncthreads();
    for (int o = 1; o < 1024; o <<= 1) {
        int v = 0;
        if (t >= o) v = part[t - o];
        __syncthreads();
        if (t >= o) part[t] += v;
        __syncthreads();
    }
    int off = (t == 0) ? 0 : part[t - 1];
#pragma unroll
    for (int i = 0; i < per; ++i) {
        int idx = base + i;
        if (idx < N_NODES) {
            int d = sdeg[idx];
            sdeg[idx] = off;
            off += d;
        }
    }
    __syncthreads();
    for (int i = t; i < N_NODES; i += 1024) {
        int v = sdeg[i];
        g_off[i] = v;
        g_cur[i] = v;
    }
    if (t == 0) g_off[N_NODES] = N_EDGES;
}

// ---------------- CSR fill (4 edges/thread for MLP) ----------------
__global__ void fill_csr() {
    int i0 = (blockIdx.x * blockDim.x + threadIdx.x) * 4;
    if (i0 + 3 < N_EDGES) {
        int4 d = *(const int4*)&g_dst[i0];
        int4 s = *(const int4*)&g_src[i0];
        int p0 = atomicAdd(&g_cur[d.x], 1);
        int p1 = atomicAdd(&g_cur[d.y], 1);
        int p2 = atomicAdd(&g_cur[d.z], 1);
        int p3 = atomicAdd(&g_cur[d.w], 1);
        g_csrc[p0] = s.x; g_csrc[p1] = s.y; g_csrc[p2] = s.z; g_csrc[p3] = s.w;
    } else {
        for (int i = i0; i < N_EDGES; ++i) {
            int p = atomicAdd(&g_cur[g_dst[i]], 1);
            g_csrc[p] = g_src[i];
        }
    }
}

// ---------------- tf32 helpers ----------------
__device__ __forceinline__ float tf32r(float x) {
    uint32_t u; asm("cvt.rna.tf32.f32 %0, %1;" : "=r"(u) : "f"(x));
    return __uint_as_float(u);
}
__device__ __forceinline__ uint32_t tf32u(float x) {
    uint32_t u; asm("cvt.rna.tf32.f32 %0, %1;" : "=r"(u) : "f"(x));
    return u;
}
__device__ __forceinline__ void mma8(float* c, uint32_t a0, uint32_t a1, uint32_t a2,
                                     uint32_t a3, uint32_t b0, uint32_t b1) {
    asm volatile("mma.sync.aligned.m16n8k8.row.col.f32.tf32.tf32.f32 "
                 "{%0,%1,%2,%3}, {%4,%5,%6,%7}, {%8,%9}, {%0,%1,%2,%3};"
                 : "+f"(c[0]), "+f"(c[1]), "+f"(c[2]), "+f"(c[3])
                 : "r"(a0), "r"(a1), "r"(a2), "r"(a3), "r"(b0), "r"(b1));
}

// ---------------- fused conv layer (tensor-core GEMMs) ----------------
#define GEMM_ROWS 64
#define ASTR 132     // A/T tile stride: A-frag LDS bank = lane (conflict-free)
#define WSTR 136     // W tile stride: B-frag LDS bank = 8k+q (conflict-free)
#define CONV_SMEM ((128 * WSTR + GEMM_ROWS * ASTR) * 4)

// warp tile: m16 x n64, k=128 in 8-steps. 2-pass tf32 split on A, W pre-rounded.
__device__ __forceinline__ void gemm_tile(const float* __restrict__ As,
                                          const float* __restrict__ Ws,
                                          float acc[8][4],
                                          int m_base, int n_base, int qid, int tid4)
{
#pragma unroll
    for (int nt = 0; nt < 8; ++nt)
#pragma unroll
        for (int j = 0; j < 4; ++j) acc[nt][j] = 0.f;

#pragma unroll 4
    for (int k0 = 0; k0 < 128; k0 += 8) {
        const float* ar0 = &As[(m_base + qid) * ASTR + k0 + tid4];
        const float* ar1 = &As[(m_base + qid + 8) * ASTR + k0 + tid4];
        float a0f = ar0[0], a1f = ar1[0], a2f = ar0[4], a3f = ar1[4];
        uint32_t a0h = tf32u(a0f), a1h = tf32u(a1f), a2h = tf32u(a2f), a3h = tf32u(a3f);
        uint32_t a0l = tf32u(a0f - __uint_as_float(a0h));
        uint32_t a1l = tf32u(a1f - __uint_as_float(a1h));
        uint32_t a2l = tf32u(a2f - __uint_as_float(a2h));
        uint32_t a3l = tf32u(a3f - __uint_as_float(a3h));
        const float* wr0 = &Ws[(k0 + tid4) * WSTR + n_base + qid];
        const float* wr1 = wr0 + 4 * WSTR;
#pragma unroll
        for (int nt = 0; nt < 8; ++nt) {
            uint32_t b0 = __float_as_uint(wr0[nt * 8]);
            uint32_t b1 = __float_as_uint(wr1[nt * 8]);
            mma8(acc[nt], a0h, a1h, a2h, a3h, b0, b1);
            mma8(acc[nt], a0l, a1l, a2l, a3l, b0, b1);
        }
    }
}

__global__ void __launch_bounds__(256, 2) fused_conv(
    const float* __restrict__ feat,
    const float* __restrict__ Wa, const float* __restrict__ ba,
    const float* __restrict__ Wb, const float* __restrict__ bb,
    float* __restrict__ out, int do_pool)
{
    extern __shared__ float sm[];
    float* Ws = sm;                  // [128][WSTR]
    float* As = sm + 128 * WSTR;     // [64][ASTR]  (A tile, then T tile)

    const int t = threadIdx.x;
    const int m0 = blockIdx.x * GEMM_ROWS;
    const int lane = t & 31;
    const int w = t >> 5;

    // ---- load Wa (pre-rounded to tf32)
#pragma unroll
    for (int i = 0; i < 16; ++i) {
        int idx = t + i * 256;
        float4 v = ((const float4*)Wa)[idx];
        int kk = idx >> 5;
        int nn = (idx & 31) * 4;
        *(float4*)&Ws[kk * WSTR + nn] =
            make_float4(tf32r(v.x), tf32r(v.y), tf32r(v.z), tf32r(v.w));
    }

    // ---- gather: warp per node, 8 nodes per warp; folds "+x" (GIN eps=0)
    const float4* fp = (const float4*)feat;
#pragma unroll
    for (int i = 0; i < 8; ++i) {
        int r = w * 8 + i;
        int node = m0 + r;
        float4 acc4 = make_float4(0.f, 0.f, 0.f, 0.f);
        if (node < N_NODES) {
            acc4 = fp[(size_t)node * 32 + lane];
            int e = g_off[node];
            int end = g_off[node + 1];
            for (; e + 4 <= end; e += 4) {
                int s0 = g_csrc[e + 0];
                int s1 = g_csrc[e + 1];
                int s2 = g_csrc[e + 2];
                int s3 = g_csrc[e + 3];
                float4 v0 = fp[(size_t)s0 * 32 + lane];
                float4 v1 = fp[(size_t)s1 * 32 + lane];
                float4 v2 = fp[(size_t)s2 * 32 + lane];
                float4 v3 = fp[(size_t)s3 * 32 + lane];
                acc4.x += v0.x + v1.x + v2.x + v3.x;
                acc4.y += v0.y + v1.y + v2.y + v3.y;
                acc4.z += v0.z + v1.z + v2.z + v3.z;
                acc4.w += v0.w + v1.w + v2.w + v3.w;
            }
            for (; e < end; ++e) {
                int s = g_csrc[e];
                float4 v = fp[(size_t)s * 32 + lane];
                acc4.x += v.x; acc4.y += v.y; acc4.z += v.z; acc4.w += v.w;
            }
        }
        *((float4*)&As[r * ASTR + lane * 4]) = acc4;
    }
    __syncthreads();

    const int warp_m = w & 3;         // 4 warps along M (16 rows each)
    const int warp_n = w >> 2;        // 2 warps along N (64 cols each)
    const int m_base = warp_m * 16;
    const int n_base = warp_n * 64;
    const int qid = lane >> 2;
    const int tid4 = lane & 3;

    float acc[8][4];

    // ---- GEMM1
    gemm_tile(As, Ws, acc, m_base, n_base, qid, tid4);
    __syncthreads();   // all GEMM1 reads of As & Ws complete

    // ---- t = relu(acc + ba) -> As ; reload Ws with Wb
#pragma unroll
    for (int nt = 0; nt < 8; ++nt) {
        int col = n_base + nt * 8 + 2 * tid4;
        float2 bv = *(const float2*)&ba[col];
        int r0 = m_base + qid, r1 = r0 + 8;
        *(float2*)&As[r0 * ASTR + col] =
            make_float2(fmaxf(acc[nt][0] + bv.x, 0.f), fmaxf(acc[nt][1] + bv.y, 0.f));
        *(float2*)&As[r1 * ASTR + col] =
            make_float2(fmaxf(acc[nt][2] + bv.x, 0.f), fmaxf(acc[nt][3] + bv.y, 0.f));
    }
#pragma unroll
    for (int i = 0; i < 16; ++i) {
        int idx = t + i * 256;
        float4 v = ((const float4*)Wb)[idx];
        int kk = idx >> 5;
        int nn = (idx & 31) * 4;
        *(float4*)&Ws[kk * WSTR + nn] =
            make_float4(tf32r(v.x), tf32r(v.y), tf32r(v.z), tf32r(v.w));
    }
    __syncthreads();

    // ---- GEMM2
    gemm_tile(As, Ws, acc, m_base, n_base, qid, tid4);

    // ---- epilogue
    const int rowA = m0 + m_base + qid;
    const int rowB = rowA + 8;
    if (do_pool) {
        int gA = (rowA < N_NODES) ? g_batch[rowA] : -1;
        int gB = (rowB < N_NODES) ? g_batch[rowB] : -1;
#pragma unroll
        for (int nt = 0; nt < 8; ++nt) {
            int col = n_base + nt * 8 + 2 * tid4;
            float2 bv = *(const float2*)&bb[col];
            float v0 = fmaxf(acc[nt][0] + bv.x, 0.f);
            float v1 = fmaxf(acc[nt][1] + bv.y, 0.f);
            float v2 = fmaxf(acc[nt][2] + bv.x, 0.f);
            float v3 = fmaxf(acc[nt][3] + bv.y, 0.f);
            if (gA >= 0 && gA == gB) {
                atomicAdd(&g_gsum[gA * C + col],     v0 + v2);
                atomicAdd(&g_gsum[gA * C + col + 1], v1 + v3);
            } else {
                if (gA >= 0) {
                    atomicAdd(&g_gsum[gA * C + col],     v0);
                    atomicAdd(&g_gsum[gA * C + col + 1], v1);
                }
                if (gB >= 0) {
                    atomicAdd(&g_gsum[gB * C + col],     v2);
                    atomicAdd(&g_gsum[gB * C + col + 1], v3);
                }
            }
        }
    } else {
#pragma unroll
        for (int nt = 0; nt < 8; ++nt) {
            int col = n_base + nt * 8 + 2 * tid4;
            float2 bv = *(const float2*)&bb[col];
            if (rowA < N_NODES)
                *(float2*)&out[(size_t)rowA * C + col] =
                    make_float2(fmaxf(acc[nt][0] + bv.x, 0.f), fmaxf(acc[nt][1] + bv.y, 0.f));
            if (rowB < N_NODES)
                *(float2*)&out[(size_t)rowB * C + col] =
                    make_float2(fmaxf(acc[nt][2] + bv.x, 0.f), fmaxf(acc[nt][3] + bv.y, 0.f));
        }
    }
}

// ---------------- finalize: out[g] = (gsum[g]/cnt[g]) . fc_w + fc_b ----------------
__global__ void finalize_kernel(const float* __restrict__ fc_w,
                                const float* __restrict__ fc_b,
                                float* __restrict__ out) {
    int g = blockIdx.x;
    int t = threadIdx.x;  // 128
    float v = g_gsum[g * C + t] * fc_w[t];
#pragma unroll
    for (int o = 16; o > 0; o >>= 1) v += __shfl_down_sync(0xFFFFFFFFu, v, o);
    __shared__ float ws[4];
    if ((t & 31) == 0) ws[t >> 5] = v;
    __syncthreads();
    if (t == 0) {
        float s = ws[0] + ws[1] + ws[2] + ws[3];
        out[g] = s / fmaxf(g_gcnt[g], 1.0f) + fc_b[0];
    }
}

// ---------------- launch ----------------
extern "C" void kernel_launch(void* const* d_in, const int* in_sizes, int n_in,
                              void* d_out, int out_size) {
    const float* x    = (const float*)d_in[0];
    const void*  eidx = d_in[1];
    const void*  batv = d_in[2];
    const float* W1a  = (const float*)d_in[3];
    const float* b1a  = (const float*)d_in[4];
    const float* W1b  = (const float*)d_in[5];
    const float* b1b  = (const float*)d_in[6];
    const float* W2a  = (const float*)d_in[7];
    const float* b2a  = (const float*)d_in[8];
    const float* W2b  = (const float*)d_in[9];
    const float* b2b  = (const float*)d_in[10];
    const float* fcw  = (const float*)d_in[11];
    const float* fcb  = (const float*)d_in[12];
    float* out = (float*)d_out;
    (void)in_sizes; (void)n_in; (void)out_size;

    cudaFuncSetAttribute(fused_conv,
                         cudaFuncAttributeMaxDynamicSharedMemorySize, CONV_SMEM);
    cudaFuncSetAttribute(scan_deg,
                         cudaFuncAttributeMaxDynamicSharedMemorySize, SCAN_SMEM);

    float* p_h;
    cudaGetSymbolAddress((void**)&p_h, g_h);

    const int conv_blocks = (N_NODES + GEMM_ROWS - 1) / GEMM_ROWS;

    // ---- CSR build (once; reused by both layers)
    setup_kernel<<<(N_NODES + 255) / 256, 256>>>((const int*)eidx);
    convert_indices<<<(N_EDGES / 4 + 255) / 256, 256>>>(eidx, batv);
    scan_deg<<<1, 1024, SCAN_SMEM>>>();
    fill_csr<<<(N_EDGES / 4 + 255) / 256, 256>>>();

    // ---- conv1 (fused gather + MLP)
    fused_conv<<<conv_blocks, 256, CONV_SMEM>>>(x, W1a, b1a, W1b, b1b, p_h, 0);
    // ---- conv2 (fused gather + MLP + pool)
    fused_conv<<<conv_blocks, 256, CONV_SMEM>>>(p_h, W2a, b2a, W2b, b2b, nullptr, 1);

    finalize_kernel<<<NUM_GRAPHS, C>>>(fcw, fcb, out);
}

// round 6
// speedup vs baseline: 3.4843x; 1.1104x over previous
#include <cuda_runtime.h>
#include <cstdint>

#define N_NODES 20000
#define N_EDGES 640000
#define C 128
#define NUM_GRAPHS 64

// ---------------- scratch (no allocations allowed) ----------------
__device__ float g_h[N_NODES * C];     // h1 (conv1 output)
__device__ float g_gsum[NUM_GRAPHS * C];
__device__ float g_gcnt[NUM_GRAPHS];
__device__ int   g_src[N_EDGES];
__device__ int   g_dst[N_EDGES];
__device__ int   g_rank[N_EDGES];      // within-dst arrival rank (from histogram atomic)
__device__ int   g_csrc[N_EDGES];      // CSR: src ids grouped by dst
__device__ int   g_off[N_NODES + 1];   // CSR row offsets
__device__ int   g_deg[N_NODES];
__device__ int   g_batch[N_NODES];
__device__ int   g_is64;

// ---------------- setup: zero accumulators + detect index dtype ----------------
__global__ void setup_kernel(const int* __restrict__ eidx_raw) {
    int i = blockIdx.x * blockDim.x + threadIdx.x;
    if (i < N_NODES) g_deg[i] = 0;
    if (i < NUM_GRAPHS * C) g_gsum[i] = 0.f;
    if (i < NUM_GRAPHS) g_gcnt[i] = 0.f;
    if (i == 0) {
        int any = 0;
#pragma unroll
        for (int k = 1; k < 128; k += 2) any |= eidx_raw[k];
        g_is64 = (any == 0) ? 1 : 0;
    }
}

// ---------------- convert indices + degree histogram (rank captured) ----------------
__global__ void convert_indices(const void* __restrict__ eidx,
                                const void* __restrict__ batch) {
    int i0 = (blockIdx.x * blockDim.x + threadIdx.x) * 4;
    if (g_is64) {
        const long long* e = (const long long*)eidx;
        if (i0 < N_EDGES) {
            longlong2 s01 = *(const longlong2*)&e[i0];
            longlong2 s23 = *(const longlong2*)&e[i0 + 2];
            longlong2 d01 = *(const longlong2*)&e[N_EDGES + i0];
            longlong2 d23 = *(const longlong2*)&e[N_EDGES + i0 + 2];
            int4 s = make_int4((int)s01.x, (int)s01.y, (int)s23.x, (int)s23.y);
            int4 d = make_int4((int)d01.x, (int)d01.y, (int)d23.x, (int)d23.y);
            *(int4*)&g_src[i0] = s;
            *(int4*)&g_dst[i0] = d;
            int4 r;
            r.x = atomicAdd(&g_deg[d.x], 1);
            r.y = atomicAdd(&g_deg[d.y], 1);
            r.z = atomicAdd(&g_deg[d.z], 1);
            r.w = atomicAdd(&g_deg[d.w], 1);
            *(int4*)&g_rank[i0] = r;
        }
        if (i0 < N_NODES) {
            const long long* b = (const long long*)batch;
            longlong2 b01 = *(const longlong2*)&b[i0];
            longlong2 b23 = *(const longlong2*)&b[i0 + 2];
            int4 g = make_int4((int)b01.x, (int)b01.y, (int)b23.x, (int)b23.y);
            *(int4*)&g_batch[i0] = g;
            atomicAdd(&g_gcnt[g.x], 1.f); atomicAdd(&g_gcnt[g.y], 1.f);
            atomicAdd(&g_gcnt[g.z], 1.f); atomicAdd(&g_gcnt[g.w], 1.f);
        }
    } else {
        const int* e = (const int*)eidx;
        if (i0 < N_EDGES) {
            int4 s = *(const int4*)&e[i0];
            int4 d = *(const int4*)&e[N_EDGES + i0];
            *(int4*)&g_src[i0] = s;
            *(int4*)&g_dst[i0] = d;
            int4 r;
            r.x = atomicAdd(&g_deg[d.x], 1);
            r.y = atomicAdd(&g_deg[d.y], 1);
            r.z = atomicAdd(&g_deg[d.z], 1);
            r.w = atomicAdd(&g_deg[d.w], 1);
            *(int4*)&g_rank[i0] = r;
        }
        if (i0 < N_NODES) {
            int4 g = *(const int4*)&((const int*)batch)[i0];
            *(int4*)&g_batch[i0] = g;
            atomicAdd(&g_gcnt[g.x], 1.f); atomicAdd(&g_gcnt[g.y], 1.f);
            atomicAdd(&g_gcnt[g.z], 1.f); atomicAdd(&g_gcnt[g.w], 1.f);
        }
    }
}

// ---------------- single-block scan, smem-staged (coalesced) ----------------
#define SCAN_SMEM (N_NODES * 4)
__global__ void __launch_bounds__(1024) scan_deg() {
    extern __shared__ int sdeg[];
    __shared__ int part[1024];
    const int t = threadIdx.x;
    const int per = (N_NODES + 1023) / 1024;   // 20

    for (int i = t; i < N_NODES; i += 1024) sdeg[i] = g_deg[i];
    __syncthreads();

    const int base = t * per;
    int s = 0;
#pragma unroll
    for (int i = 0; i < per; ++i) {
        int idx = base + i;
        if (idx < N_NODES) s += sdeg[idx];
    }
    part[t] = s;
    __syncthreads();
    for (int o = 1; o < 1024; o <<= 1) {
        int v = 0;
        if (t >= o) v = part[t - o];
        __syncthreads();
        if (t >= o) part[t] += v;
        __syncthreads();
    }
    int off = (t == 0) ? 0 : part[t - 1];
#pragma unroll
    for (int i = 0; i < per; ++i) {
        int idx = base + i;
        if (idx < N_NODES) {
            int d = sdeg[idx];
            sdeg[idx] = off;
            off += d;
        }
    }
    __syncthreads();
    for (int i = t; i < N_NODES; i += 1024) g_off[i] = sdeg[i];
    if (t == 0) g_off[N_NODES] = N_EDGES;
}

// ---------------- CSR fill: atomic-free (pos = off[dst] + rank) ----------------
__global__ void fill_csr() {
    int i0 = (blockIdx.x * blockDim.x + threadIdx.x) * 4;
    if (i0 + 3 < N_EDGES) {
        int4 d = *(const int4*)&g_dst[i0];
        int4 s = *(const int4*)&g_src[i0];
        int4 r = *(const int4*)&g_rank[i0];
        g_csrc[g_off[d.x] + r.x] = s.x;
        g_csrc[g_off[d.y] + r.y] = s.y;
        g_csrc[g_off[d.z] + r.z] = s.z;
        g_csrc[g_off[d.w] + r.w] = s.w;
    } else {
        for (int i = i0; i < N_EDGES; ++i)
            g_csrc[g_off[g_dst[i]] + g_rank[i]] = g_src[i];
    }
}

// ---------------- tf32 helpers ----------------
__device__ __forceinline__ float tf32r(float x) {
    uint32_t u; asm("cvt.rna.tf32.f32 %0, %1;" : "=r"(u) : "f"(x));
    return __uint_as_float(u);
}
__device__ __forceinline__ uint32_t tf32u(float x) {
    uint32_t u; asm("cvt.rna.tf32.f32 %0, %1;" : "=r"(u) : "f"(x));
    return u;
}
__device__ __forceinline__ void mma8(float* c, uint32_t a0, uint32_t a1, uint32_t a2,
                                     uint32_t a3, uint32_t b0, uint32_t b1) {
    asm volatile("mma.sync.aligned.m16n8k8.row.col.f32.tf32.tf32.f32 "
                 "{%0,%1,%2,%3}, {%4,%5,%6,%7}, {%8,%9}, {%0,%1,%2,%3};"
                 : "+f"(c[0]), "+f"(c[1]), "+f"(c[2]), "+f"(c[3])
                 : "r"(a0), "r"(a1), "r"(a2), "r"(a3), "r"(b0), "r"(b1));
}

// ---------------- fused conv layer (tensor-core GEMMs, 32-row tiles) ----------------
// 20000 / 32 = 625 tiles exactly -> no ragged tail tile; work-stealing over
// 2.11 waves at 2 CTAs/SM removes the 2x wave-quantization of 64-row tiles.
#define TILE_ROWS 32
#define ASTR 132     // A/T tile stride: A-frag LDS bank = lane (conflict-free)
#define WSTR 136     // W tile stride: B-frag LDS bank = 8k+q (conflict-free)
#define CONV_SMEM ((128 * WSTR + TILE_ROWS * ASTR) * 4)

// warp tile: m16 x n32, k=128 in 8-steps; 2-pass tf32 split on A, W pre-rounded.
__device__ __forceinline__ void gemm_tile(const float* __restrict__ As,
                                          const float* __restrict__ Ws,
                                          float acc[4][4],
                                          int m_base, int n_base, int qid, int tid4)
{
#pragma unroll
    for (int nt = 0; nt < 4; ++nt)
#pragma unroll
        for (int j = 0; j < 4; ++j) acc[nt][j] = 0.f;

#pragma unroll 4
    for (int k0 = 0; k0 < 128; k0 += 8) {
        const float* ar0 = &As[(m_base + qid) * ASTR + k0 + tid4];
        const float* ar1 = &As[(m_base + qid + 8) * ASTR + k0 + tid4];
        float a0f = ar0[0], a1f = ar1[0], a2f = ar0[4], a3f = ar1[4];
        uint32_t a0h = tf32u(a0f), a1h = tf32u(a1f), a2h = tf32u(a2f), a3h = tf32u(a3f);
        uint32_t a0l = tf32u(a0f - __uint_as_float(a0h));
        uint32_t a1l = tf32u(a1f - __uint_as_float(a1h));
        uint32_t a2l = tf32u(a2f - __uint_as_float(a2h));
        uint32_t a3l = tf32u(a3f - __uint_as_float(a3h));
        const float* wr0 = &Ws[(k0 + tid4) * WSTR + n_base + qid];
        const float* wr1 = wr0 + 4 * WSTR;
#pragma unroll
        for (int nt = 0; nt < 4; ++nt) {
            uint32_t b0 = __float_as_uint(wr0[nt * 8]);
            uint32_t b1 = __float_as_uint(wr1[nt * 8]);
            mma8(acc[nt], a0h, a1h, a2h, a3h, b0, b1);
            mma8(acc[nt], a0l, a1l, a2l, a3l, b0, b1);
        }
    }
}

__global__ void __launch_bounds__(256, 2) fused_conv(
    const float* __restrict__ feat,
    const float* __restrict__ Wa, const float* __restrict__ ba,
    const float* __restrict__ Wb, const float* __restrict__ bb,
    float* __restrict__ out, int do_pool)
{
    extern __shared__ float sm[];
    float* Ws = sm;                       // [128][WSTR]
    float* As = sm + 128 * WSTR;          // [32][ASTR] (A tile, then T tile)

    const int t = threadIdx.x;
    const int m0 = blockIdx.x * TILE_ROWS;
    const int lane = t & 31;
    const int w = t >> 5;

    // ---- load Wa (pre-rounded to tf32)
#pragma unroll
    for (int i = 0; i < 16; ++i) {
        int idx = t + i * 256;
        float4 v = ((const float4*)Wa)[idx];
        int kk = idx >> 5;
        int nn = (idx & 31) * 4;
        *(float4*)&Ws[kk * WSTR + nn] =
            make_float4(tf32r(v.x), tf32r(v.y), tf32r(v.z), tf32r(v.w));
    }

    // ---- gather: warp per node, 4 nodes per warp; folds "+x" (GIN eps=0)
    const float4* fp = (const float4*)feat;
#pragma unroll
    for (int i = 0; i < 4; ++i) {
        int r = w * 4 + i;                // local row 0..31
        int node = m0 + r;                // always < N_NODES (20000 = 625*32)
        float4 acc4 = fp[(size_t)node * 32 + lane];
        int e = g_off[node];
        int end = g_off[node + 1];
        for (; e + 4 <= end; e += 4) {
            int s0 = g_csrc[e + 0];
            int s1 = g_csrc[e + 1];
            int s2 = g_csrc[e + 2];
            int s3 = g_csrc[e + 3];
            float4 v0 = fp[(size_t)s0 * 32 + lane];
            float4 v1 = fp[(size_t)s1 * 32 + lane];
            float4 v2 = fp[(size_t)s2 * 32 + lane];
            float4 v3 = fp[(size_t)s3 * 32 + lane];
            acc4.x += v0.x + v1.x + v2.x + v3.x;
            acc4.y += v0.y + v1.y + v2.y + v3.y;
            acc4.z += v0.z + v1.z + v2.z + v3.z;
            acc4.w += v0.w + v1.w + v2.w + v3.w;
        }
        for (; e < end; ++e) {
            int s = g_csrc[e];
            float4 v = fp[(size_t)s * 32 + lane];
            acc4.x += v.x; acc4.y += v.y; acc4.z += v.z; acc4.w += v.w;
        }
        *((float4*)&As[r * ASTR + lane * 4]) = acc4;
    }
    __syncthreads();

    const int warp_m = w & 1;             // 2 warps along M (16 rows each)
    const int warp_n = w >> 1;            // 4 warps along N (32 cols each)
    const int m_base = warp_m * 16;
    const int n_base = warp_n * 32;
    const int qid = lane >> 2;
    const int tid4 = lane & 3;

    float acc[4][4];

    // ---- GEMM1
    gemm_tile(As, Ws, acc, m_base, n_base, qid, tid4);
    __syncthreads();   // all GEMM1 reads of As & Ws complete

    // ---- t = relu(acc + ba) -> As ; reload Ws with Wb
#pragma unroll
    for (int nt = 0; nt < 4; ++nt) {
        int col = n_base + nt * 8 + 2 * tid4;
        float2 bv = *(const float2*)&ba[col];
        int r0 = m_base + qid, r1 = r0 + 8;
        *(float2*)&As[r0 * ASTR + col] =
            make_float2(fmaxf(acc[nt][0] + bv.x, 0.f), fmaxf(acc[nt][1] + bv.y, 0.f));
        *(float2*)&As[r1 * ASTR + col] =
            make_float2(fmaxf(acc[nt][2] + bv.x, 0.f), fmaxf(acc[nt][3] + bv.y, 0.f));
    }
#pragma unroll
    for (int i = 0; i < 16; ++i) {
        int idx = t + i * 256;
        float4 v = ((const float4*)Wb)[idx];
        int kk = idx >> 5;
        int nn = (idx & 31) * 4;
        *(float4*)&Ws[kk * WSTR + nn] =
            make_float4(tf32r(v.x), tf32r(v.y), tf32r(v.z), tf32r(v.w));
    }
    __syncthreads();

    // ---- GEMM2
    gemm_tile(As, Ws, acc, m_base, n_base, qid, tid4);

    // ---- epilogue
    const int rowA = m0 + m_base + qid;
    const int rowB = rowA + 8;
    if (do_pool) {
        int gA = g_batch[rowA];
        int gB = g_batch[rowB];
#pragma unroll
        for (int nt = 0; nt < 4; ++nt) {
            int col = n_base + nt * 8 + 2 * tid4;
            float2 bv = *(const float2*)&bb[col];
            float v0 = fmaxf(acc[nt][0] + bv.x, 0.f);
            float v1 = fmaxf(acc[nt][1] + bv.y, 0.f);
            float v2 = fmaxf(acc[nt][2] + bv.x, 0.f);
            float v3 = fmaxf(acc[nt][3] + bv.y, 0.f);
            if (gA == gB) {
                atomicAdd(&g_gsum[gA * C + col],     v0 + v2);
                atomicAdd(&g_gsum[gA * C + col + 1], v1 + v3);
            } else {
                atomicAdd(&g_gsum[gA * C + col],     v0);
                atomicAdd(&g_gsum[gA * C + col + 1], v1);
                atomicAdd(&g_gsum[gB * C + col],     v2);
                atomicAdd(&g_gsum[gB * C + col + 1], v3);
            }
        }
    } else {
#pragma unroll
        for (int nt = 0; nt < 4; ++nt) {
            int col = n_base + nt * 8 + 2 * tid4;
            float2 bv = *(const float2*)&bb[col];
            *(float2*)&out[(size_t)rowA * C + col] =
                make_float2(fmaxf(acc[nt][0] + bv.x, 0.f), fmaxf(acc[nt][1] + bv.y, 0.f));
            *(float2*)&out[(size_t)rowB * C + col] =
                make_float2(fmaxf(acc[nt][2] + bv.x, 0.f), fmaxf(acc[nt][3] + bv.y, 0.f));
        }
    }
}

// ---------------- finalize: out[g] = (gsum[g]/cnt[g]) . fc_w + fc_b ----------------
__global__ void finalize_kernel(const float* __restrict__ fc_w,
                                const float* __restrict__ fc_b,
                                float* __restrict__ out) {
    int g = blockIdx.x;
    int t = threadIdx.x;  // 128
    float v = g_gsum[g * C + t] * fc_w[t];
#pragma unroll
    for (int o = 16; o > 0; o >>= 1) v += __shfl_down_sync(0xFFFFFFFFu, v, o);
    __shared__ float ws[4];
    if ((t & 31) == 0) ws[t >> 5] = v;
    __syncthreads();
    if (t == 0) {
        float s = ws[0] + ws[1] + ws[2] + ws[3];
        out[g] = s / fmaxf(g_gcnt[g], 1.0f) + fc_b[0];
    }
}

// ---------------- launch ----------------
extern "C" void kernel_launch(void* const* d_in, const int* in_sizes, int n_in,
                              void* d_out, int out_size) {
    const float* x    = (const float*)d_in[0];
    const void*  eidx = d_in[1];
    const void*  batv = d_in[2];
    const float* W1a  = (const float*)d_in[3];
    const float* b1a  = (const float*)d_in[4];
    const float* W1b  = (const float*)d_in[5];
    const float* b1b  = (const float*)d_in[6];
    const float* W2a  = (const float*)d_in[7];
    const float* b2a  = (const float*)d_in[8];
    const float* W2b  = (const float*)d_in[9];
    const float* b2b  = (const float*)d_in[10];
    const float* fcw  = (const float*)d_in[11];
    const float* fcb  = (const float*)d_in[12];
    float* out = (float*)d_out;
    (void)in_sizes; (void)n_in; (void)out_size;

    cudaFuncSetAttribute(fused_conv,
                         cudaFuncAttributeMaxDynamicSharedMemorySize, CONV_SMEM);
    cudaFuncSetAttribute(scan_deg,
                         cudaFuncAttributeMaxDynamicSharedMemorySize, SCAN_SMEM);

    float* p_h;
    cudaGetSymbolAddress((void**)&p_h, g_h);

    const int conv_blocks = N_NODES / TILE_ROWS;   // 625, exact

    // ---- CSR build (once; reused by both layers)
    setup_kernel<<<(N_NODES + 255) / 256, 256>>>((const int*)eidx);
    convert_indices<<<(N_EDGES / 4 + 255) / 256, 256>>>(eidx, batv);
    scan_deg<<<1, 1024, SCAN_SMEM>>>();
    fill_csr<<<(N_EDGES / 4 + 255) / 256, 256>>>();

    // ---- conv1 (fused gather + MLP)
    fused_conv<<<conv_blocks, 256, CONV_SMEM>>>(x, W1a, b1a, W1b, b1b, p_h, 0);
    // ---- conv2 (fused gather + MLP + pool)
    fused_conv<<<conv_blocks, 256, CONV_SMEM>>>(p_h, W2a, b2a, W2b, b2b, nullptr, 1);

    finalize_kernel<<<NUM_GRAPHS, C>>>(fcw, fcb, out);
}

// round 7
// speedup vs baseline: 3.7215x; 1.0681x over previous
#include <cuda_runtime.h>
#include <cstdint>

#define N_NODES 20000
#define N_EDGES 640000
#define C 128
#define NUM_GRAPHS 64

// ---------------- scratch (no allocations allowed) ----------------
__device__ float g_h[N_NODES * C];     // h1 (conv1 output)
__device__ float g_gsum[NUM_GRAPHS * C];
__device__ float g_gcnt[NUM_GRAPHS];
__device__ int   g_src[N_EDGES];
__device__ int   g_dst[N_EDGES];
__device__ int   g_rank[N_EDGES];      // within-dst arrival rank (from histogram atomic)
__device__ int   g_csrc[N_EDGES];      // CSR: src ids grouped by dst
__device__ int   g_off[N_NODES + 1];   // CSR row offsets
__device__ int   g_deg[N_NODES];
__device__ int   g_batch[N_NODES];
__device__ int   g_is64;

// ---------------- setup: zero accumulators + detect index dtype ----------------
__global__ void setup_kernel(const int* __restrict__ eidx_raw) {
    int i = blockIdx.x * blockDim.x + threadIdx.x;
    if (i < N_NODES) g_deg[i] = 0;
    if (i < NUM_GRAPHS * C) g_gsum[i] = 0.f;
    if (i < NUM_GRAPHS) g_gcnt[i] = 0.f;
    if (i == 0) {
        int any = 0;
#pragma unroll
        for (int k = 1; k < 128; k += 2) any |= eidx_raw[k];
        g_is64 = (any == 0) ? 1 : 0;
    }
}

// ---------------- convert indices + degree histogram (rank captured) ----------------
__global__ void convert_indices(const void* __restrict__ eidx,
                                const void* __restrict__ batch) {
    int i0 = (blockIdx.x * blockDim.x + threadIdx.x) * 4;
    if (g_is64) {
        const long long* e = (const long long*)eidx;
        if (i0 < N_EDGES) {
            longlong2 s01 = *(const longlong2*)&e[i0];
            longlong2 s23 = *(const longlong2*)&e[i0 + 2];
            longlong2 d01 = *(const longlong2*)&e[N_EDGES + i0];
            longlong2 d23 = *(const longlong2*)&e[N_EDGES + i0 + 2];
            int4 s = make_int4((int)s01.x, (int)s01.y, (int)s23.x, (int)s23.y);
            int4 d = make_int4((int)d01.x, (int)d01.y, (int)d23.x, (int)d23.y);
            *(int4*)&g_src[i0] = s;
            *(int4*)&g_dst[i0] = d;
            int4 r;
            r.x = atomicAdd(&g_deg[d.x], 1);
            r.y = atomicAdd(&g_deg[d.y], 1);
            r.z = atomicAdd(&g_deg[d.z], 1);
            r.w = atomicAdd(&g_deg[d.w], 1);
            *(int4*)&g_rank[i0] = r;
        }
        if (i0 < N_NODES) {
            const long long* b = (const long long*)batch;
            longlong2 b01 = *(const longlong2*)&b[i0];
            longlong2 b23 = *(const longlong2*)&b[i0 + 2];
            int4 g = make_int4((int)b01.x, (int)b01.y, (int)b23.x, (int)b23.y);
            *(int4*)&g_batch[i0] = g;
            atomicAdd(&g_gcnt[g.x], 1.f); atomicAdd(&g_gcnt[g.y], 1.f);
            atomicAdd(&g_gcnt[g.z], 1.f); atomicAdd(&g_gcnt[g.w], 1.f);
        }
    } else {
        const int* e = (const int*)eidx;
        if (i0 < N_EDGES) {
            int4 s = *(const int4*)&e[i0];
            int4 d = *(const int4*)&e[N_EDGES + i0];
            *(int4*)&g_src[i0] = s;
            *(int4*)&g_dst[i0] = d;
            int4 r;
            r.x = atomicAdd(&g_deg[d.x], 1);
            r.y = atomicAdd(&g_deg[d.y], 1);
            r.z = atomicAdd(&g_deg[d.z], 1);
            r.w = atomicAdd(&g_deg[d.w], 1);
            *(int4*)&g_rank[i0] = r;
        }
        if (i0 < N_NODES) {
            int4 g = *(const int4*)&((const int*)batch)[i0];
            *(int4*)&g_batch[i0] = g;
            atomicAdd(&g_gcnt[g.x], 1.f); atomicAdd(&g_gcnt[g.y], 1.f);
            atomicAdd(&g_gcnt[g.z], 1.f); atomicAdd(&g_gcnt[g.w], 1.f);
        }
    }
}

// ---------------- single-block scan, smem-staged (coalesced) ----------------
#define SCAN_SMEM (N_NODES * 4)
__global__ void __launch_bounds__(1024) scan_deg() {
    extern __shared__ int sdeg[];
    __shared__ int part[1024];
    const int t = threadIdx.x;
    const int per = (N_NODES + 1023) / 1024;   // 20

    for (int i = t; i < N_NODES; i += 1024) sdeg[i] = g_deg[i];
    __syncthreads();

    const int base = t * per;
    int s = 0;
#pragma unroll
    for (int i = 0; i < per; ++i) {
        int idx = base + i;
        if (idx < N_NODES) s += sdeg[idx];
    }
    part[t] = s;
    __syncthreads();
    for (int o = 1; o < 1024; o <<= 1) {
        int v = 0;
        if (t >= o) v = part[t - o];
        __syncthreads();
        if (t >= o) part[t] += v;
        __syncthreads();
    }
    int off = (t == 0) ? 0 : part[t - 1];
#pragma unroll
    for (int i = 0; i < per; ++i) {
        int idx = base + i;
        if (idx < N_NODES) {
            int d = sdeg[idx];
            sdeg[idx] = off;
            off += d;
        }
    }
    __syncthreads();
    for (int i = t; i < N_NODES; i += 1024) g_off[i] = sdeg[i];
    if (t == 0) g_off[N_NODES] = N_EDGES;
}

// ---------------- CSR fill: atomic-free (pos = off[dst] + rank), 2 edges/thread ----------------
__global__ void fill_csr() {
    int i0 = (blockIdx.x * blockDim.x + threadIdx.x) * 2;
    if (i0 + 1 < N_EDGES) {
        int2 d = *(const int2*)&g_dst[i0];
        int2 s = *(const int2*)&g_src[i0];
        int2 r = *(const int2*)&g_rank[i0];
        g_csrc[g_off[d.x] + r.x] = s.x;
        g_csrc[g_off[d.y] + r.y] = s.y;
    } else if (i0 < N_EDGES) {
        g_csrc[g_off[g_dst[i0]] + g_rank[i0]] = g_src[i0];
    }
}

// ---------------- tf32 helpers ----------------
__device__ __forceinline__ float tf32r(float x) {
    uint32_t u; asm("cvt.rna.tf32.f32 %0, %1;" : "=r"(u) : "f"(x));
    return __uint_as_float(u);
}
__device__ __forceinline__ void mma8(float* c, uint32_t a0, uint32_t a1, uint32_t a2,
                                     uint32_t a3, uint32_t b0, uint32_t b1) {
    asm volatile("mma.sync.aligned.m16n8k8.row.col.f32.tf32.tf32.f32 "
                 "{%0,%1,%2,%3}, {%4,%5,%6,%7}, {%8,%9}, {%0,%1,%2,%3};"
                 : "+f"(c[0]), "+f"(c[1]), "+f"(c[2]), "+f"(c[3])
                 : "r"(a0), "r"(a1), "r"(a2), "r"(a3), "r"(b0), "r"(b1));
}

// ---------------- fused conv layer (tensor-core GEMMs, 32-row tiles) ----------------
// 20000 / 32 = 625 tiles exactly. Single-pass tf32: A tiles are pre-rounded
// to tf32 at smem-write time (gather / T epilogue), W pre-rounded at load.
// Inner loop = pure LDS + HMMA.
#define TILE_ROWS 32
#define ASTR 132     // A/T tile stride: A-frag LDS bank = lane (conflict-free)
#define WSTR 136     // W tile stride: B-frag LDS bank = 8k+q (conflict-free)
#define CONV_SMEM ((128 * WSTR + TILE_ROWS * ASTR) * 4)

// warp tile: m16 x n32, k=128 in 8-steps; operands already tf32-rounded in smem.
__device__ __forceinline__ void gemm_tile(const float* __restrict__ As,
                                          const float* __restrict__ Ws,
                                          float acc[4][4],
                                          int m_base, int n_base, int qid, int tid4)
{
#pragma unroll
    for (int nt = 0; nt < 4; ++nt)
#pragma unroll
        for (int j = 0; j < 4; ++j) acc[nt][j] = 0.f;

#pragma unroll
    for (int k0 = 0; k0 < 128; k0 += 8) {
        const float* ar0 = &As[(m_base + qid) * ASTR + k0 + tid4];
        const float* ar1 = &As[(m_base + qid + 8) * ASTR + k0 + tid4];
        uint32_t a0 = __float_as_uint(ar0[0]);
        uint32_t a1 = __float_as_uint(ar1[0]);
        uint32_t a2 = __float_as_uint(ar0[4]);
        uint32_t a3 = __float_as_uint(ar1[4]);
        const float* wr0 = &Ws[(k0 + tid4) * WSTR + n_base + qid];
        const float* wr1 = wr0 + 4 * WSTR;
#pragma unroll
        for (int nt = 0; nt < 4; ++nt) {
            uint32_t b0 = __float_as_uint(wr0[nt * 8]);
            uint32_t b1 = __float_as_uint(wr1[nt * 8]);
            mma8(acc[nt], a0, a1, a2, a3, b0, b1);
        }
    }
}

__global__ void __launch_bounds__(256, 2) fused_conv(
    const float* __restrict__ feat,
    const float* __restrict__ Wa, const float* __restrict__ ba,
    const float* __restrict__ Wb, const float* __restrict__ bb,
    float* __restrict__ out, int do_pool)
{
    extern __shared__ float sm[];
    float* Ws = sm;                       // [128][WSTR]
    float* As = sm + 128 * WSTR;          // [32][ASTR] (A tile, then T tile)

    const int t = threadIdx.x;
    const int m0 = blockIdx.x * TILE_ROWS;
    const int lane = t & 31;
    const int w = t >> 5;

    // ---- load Wa (pre-rounded to tf32)
#pragma unroll
    for (int i = 0; i < 16; ++i) {
        int idx = t + i * 256;
        float4 v = ((const float4*)Wa)[idx];
        int kk = idx >> 5;
        int nn = (idx & 31) * 4;
        *(float4*)&Ws[kk * WSTR + nn] =
            make_float4(tf32r(v.x), tf32r(v.y), tf32r(v.z), tf32r(v.w));
    }

    // ---- gather: warp per node, 4 nodes per warp; folds "+x" (GIN eps=0)
    // fp32 accumulation, tf32-rounded once at the smem write.
    const float4* fp = (const float4*)feat;
#pragma unroll
    for (int i = 0; i < 4; ++i) {
        int r = w * 4 + i;                // local row 0..31
        int node = m0 + r;                // always < N_NODES (20000 = 625*32)
        float4 acc4 = fp[(size_t)node * 32 + lane];
        int e = g_off[node];
        int end = g_off[node + 1];
        for (; e + 4 <= end; e += 4) {
            int s0 = g_csrc[e + 0];
            int s1 = g_csrc[e + 1];
            int s2 = g_csrc[e + 2];
            int s3 = g_csrc[e + 3];
            float4 v0 = fp[(size_t)s0 * 32 + lane];
            float4 v1 = fp[(size_t)s1 * 32 + lane];
            float4 v2 = fp[(size_t)s2 * 32 + lane];
            float4 v3 = fp[(size_t)s3 * 32 + lane];
            acc4.x += v0.x + v1.x + v2.x + v3.x;
            acc4.y += v0.y + v1.y + v2.y + v3.y;
            acc4.z += v0.z + v1.z + v2.z + v3.z;
            acc4.w += v0.w + v1.w + v2.w + v3.w;
        }
        for (; e < end; ++e) {
            int s = g_csrc[e];
            float4 v = fp[(size_t)s * 32 + lane];
            acc4.x += v.x; acc4.y += v.y; acc4.z += v.z; acc4.w += v.w;
        }
        *((float4*)&As[r * ASTR + lane * 4]) =
            make_float4(tf32r(acc4.x), tf32r(acc4.y), tf32r(acc4.z), tf32r(acc4.w));
    }
    __syncthreads();

    const int warp_m = w & 1;             // 2 warps along M (16 rows each)
    const int warp_n = w >> 1;            // 4 warps along N (32 cols each)
    const int m_base = warp_m * 16;
    const int n_base = warp_n * 32;
    const int qid = lane >> 2;
    const int tid4 = lane & 3;

    float acc[4][4];

    // ---- GEMM1
    gemm_tile(As, Ws, acc, m_base, n_base, qid, tid4);
    __syncthreads();   // all GEMM1 reads of As & Ws complete

    // ---- t = tf32(relu(acc + ba)) -> As ; reload Ws with Wb
#pragma unroll
    for (int nt = 0; nt < 4; ++nt) {
        int col = n_base + nt * 8 + 2 * tid4;
        float2 bv = *(const float2*)&ba[col];
        int r0 = m_base + qid, r1 = r0 + 8;
        *(float2*)&As[r0 * ASTR + col] =
            make_float2(tf32r(fmaxf(acc[nt][0] + bv.x, 0.f)),
                        tf32r(fmaxf(acc[nt][1] + bv.y, 0.f)));
        *(float2*)&As[r1 * ASTR + col] =
            make_float2(tf32r(fmaxf(acc[nt][2] + bv.x, 0.f)),
                        tf32r(fmaxf(acc[nt][3] + bv.y, 0.f)));
    }
#pragma unroll
    for (int i = 0; i < 16; ++i) {
        int idx = t + i * 256;
        float4 v = ((const float4*)Wb)[idx];
        int kk = idx >> 5;
        int nn = (idx & 31) * 4;
        *(float4*)&Ws[kk * WSTR + nn] =
            make_float4(tf32r(v.x), tf32r(v.y), tf32r(v.z), tf32r(v.w));
    }
    __syncthreads();

    // ---- GEMM2
    gemm_tile(As, Ws, acc, m_base, n_base, qid, tid4);

    // ---- epilogue
    const int rowA = m0 + m_base + qid;
    const int rowB = rowA + 8;
    if (do_pool) {
        int gA = g_batch[rowA];
        int gB = g_batch[rowB];
#pragma unroll
        for (int nt = 0; nt < 4; ++nt) {
            int col = n_base + nt * 8 + 2 * tid4;
            float2 bv = *(const float2*)&bb[col];
            float v0 = fmaxf(acc[nt][0] + bv.x, 0.f);
            float v1 = fmaxf(acc[nt][1] + bv.y, 0.f);
            float v2 = fmaxf(acc[nt][2] + bv.x, 0.f);
            float v3 = fmaxf(acc[nt][3] + bv.y, 0.f);
            if (gA == gB) {
                atomicAdd(&g_gsum[gA * C + col],     v0 + v2);
                atomicAdd(&g_gsum[gA * C + col + 1], v1 + v3);
            } else {
                atomicAdd(&g_gsum[gA * C + col],     v0);
                atomicAdd(&g_gsum[gA * C + col + 1], v1);
                atomicAdd(&g_gsum[gB * C + col],     v2);
                atomicAdd(&g_gsum[gB * C + col + 1], v3);
            }
        }
    } else {
#pragma unroll
        for (int nt = 0; nt < 4; ++nt) {
            int col = n_base + nt * 8 + 2 * tid4;
            float2 bv = *(const float2*)&bb[col];
            *(float2*)&out[(size_t)rowA * C + col] =
                make_float2(fmaxf(acc[nt][0] + bv.x, 0.f), fmaxf(acc[nt][1] + bv.y, 0.f));
            *(float2*)&out[(size_t)rowB * C + col] =
                make_float2(fmaxf(acc[nt][2] + bv.x, 0.f), fmaxf(acc[nt][3] + bv.y, 0.f));
        }
    }
}

// ---------------- finalize: out[g] = (gsum[g]/cnt[g]) . fc_w + fc_b ----------------
__global__ void finalize_kernel(const float* __restrict__ fc_w,
                                const float* __restrict__ fc_b,
                                float* __restrict__ out) {
    int g = blockIdx.x;
    int t = threadIdx.x;  // 128
    float v = g_gsum[g * C + t] * fc_w[t];
#pragma unroll
    for (int o = 16; o > 0; o >>= 1) v += __shfl_down_sync(0xFFFFFFFFu, v, o);
    __shared__ float ws[4];
    if ((t & 31) == 0) ws[t >> 5] = v;
    __syncthreads();
    if (t == 0) {
        float s = ws[0] + ws[1] + ws[2] + ws[3];
        out[g] = s / fmaxf(g_gcnt[g], 1.0f) + fc_b[0];
    }
}

// ---------------- launch ----------------
extern "C" void kernel_launch(void* const* d_in, const int* in_sizes, int n_in,
                              void* d_out, int out_size) {
    const float* x    = (const float*)d_in[0];
    const void*  eidx = d_in[1];
    const void*  batv = d_in[2];
    const float* W1a  = (const float*)d_in[3];
    const float* b1a  = (const float*)d_in[4];
    const float* W1b  = (const float*)d_in[5];
    const float* b1b  = (const float*)d_in[6];
    const float* W2a  = (const float*)d_in[7];
    const float* b2a  = (const float*)d_in[8];
    const float* W2b  = (const float*)d_in[9];
    const float* b2b  = (const float*)d_in[10];
    const float* fcw  = (const float*)d_in[11];
    const float* fcb  = (const float*)d_in[12];
    float* out = (float*)d_out;
    (void)in_sizes; (void)n_in; (void)out_size;

    cudaFuncSetAttribute(fused_conv,
                         cudaFuncAttributeMaxDynamicSharedMemorySize, CONV_SMEM);
    cudaFuncSetAttribute(scan_deg,
                         cudaFuncAttributeMaxDynamicSharedMemorySize, SCAN_SMEM);

    float* p_h;
    cudaGetSymbolAddress((void**)&p_h, g_h);

    const int conv_blocks = N_NODES / TILE_ROWS;   // 625, exact

    // ---- CSR build (once; reused by both layers)
    setup_kernel<<<(N_NODES + 255) / 256, 256>>>((const int*)eidx);
    convert_indices<<<(N_EDGES / 4 + 255) / 256, 256>>>(eidx, batv);
    scan_deg<<<1, 1024, SCAN_SMEM>>>();
    fill_csr<<<(N_EDGES / 2 + 255) / 256, 256>>>();

    // ---- conv1 (fused gather + MLP)
    fused_conv<<<conv_blocks, 256, CONV_SMEM>>>(x, W1a, b1a, W1b, b1b, p_h, 0);
    // ---- conv2 (fused gather + MLP + pool)
    fused_conv<<<conv_blocks, 256, CONV_SMEM>>>(p_h, W2a, b2a, W2b, b2b, nullptr, 1);

    finalize_kernel<<<NUM_GRAPHS, C>>>(fcw, fcb, out);
}